// round 4
// baseline (speedup 1.0000x reference)
#include <cuda_runtime.h>
#include <cuda_bf16.h>
#include <cstdint>
#include <cstddef>

// ============================================================================
// HolographicMemory on GB300, base-sm_103-compatible path:
//   mma.sync (HMMA) + ldmatrix + cp.async double-buffered pipeline.
//
//   x        : [4,8192,1024] fp32  (32768 rows x 1024)
//   keys_*   : [512, 512] fp32 ;  values_* : [512, 512] fp32
//   out      : [32768, 1024] fp32
//
//   prep : g_Xbf = bf16(x); g_Kbf[512x1024] = bf16([kr|ki]);
//          g_VT[1024x512] = bf16(V^T); g_vbar[1024] = colmean(V) fp32
//   G1   : energy = Xbf * Kbf^T ; softmax; g_d = attn - 1/512 (bf16)
//   G2   : out = vbar + g_d * V   (B = VT)
// ============================================================================

#define TEMPERATURE 0.04419417382415922f   // 1/sqrt(512)
#define INV512      0.001953125f

// ---------------- device scratch (no allocation allowed) --------------------
__device__ __nv_bfloat16 g_Xbf[(size_t)32768 * 1024];
__device__ __nv_bfloat16 g_Kbf[512 * 1024];
__device__ __nv_bfloat16 g_VT[1024 * 512];
__device__ float         g_vbar[1024];
__device__ __nv_bfloat16 g_d[(size_t)32768 * 512];

// ---------------- helpers ---------------------------------------------------
__device__ __forceinline__ uint32_t smem_u32(const void* p) {
    uint32_t a;
    asm("{ .reg .u64 t; cvta.to.shared.u64 t, %1; cvt.u32.u64 %0, t; }" : "=r"(a) : "l"(p));
    return a;
}
__device__ __forceinline__ uint32_t SWZ(uint32_t x) { return x ^ ((x >> 3) & 0x70); }

#define CP_ASYNC16(dst_u32, src_ptr) \
    asm volatile("cp.async.cg.shared.global [%0], [%1], 16;" :: "r"(dst_u32), "l"(src_ptr) : "memory")
#define CP_COMMIT() asm volatile("cp.async.commit_group;" ::: "memory")
#define CP_WAIT1()  asm volatile("cp.async.wait_group 1;" ::: "memory")
#define CP_WAIT0()  asm volatile("cp.async.wait_group 0;" ::: "memory")

#define LDSM_X4(R, addr) \
    asm volatile("ldmatrix.sync.aligned.m8n8.x4.shared.b16 {%0,%1,%2,%3}, [%4];" \
        : "=r"((R)[0]), "=r"((R)[1]), "=r"((R)[2]), "=r"((R)[3]) : "r"(addr))

__device__ __forceinline__ void mma16816(float* c, const uint32_t* a, uint32_t b0, uint32_t b1) {
    asm volatile(
        "mma.sync.aligned.m16n8k16.row.col.f32.bf16.bf16.f32 "
        "{%0,%1,%2,%3}, {%4,%5,%6,%7}, {%8,%9}, {%0,%1,%2,%3};"
        : "+f"(c[0]), "+f"(c[1]), "+f"(c[2]), "+f"(c[3])
        : "r"(a[0]), "r"(a[1]), "r"(a[2]), "r"(a[3]), "r"(b0), "r"(b1));
}

// ---------------- smem layout -----------------------------------------------
// A buf: 64 rows x 64 cols bf16 = 8 KB (x2).  B buf: 512 x 64 bf16 = 64 KB (x2).
static constexpr int SMEM_BYTES = 8192 * 2 + 65536 * 2;   // 147456

// ============================================================================
// prep kernel: grid 3584 x 256
//   b in [0,2048): convert x -> g_Xbf (16384 floats per block)
//   b in [2048,3072): VT row h + vbar[h]
//   b in [3072,3584): Kbf row m
// ============================================================================
__global__ void prep_kernel(const float* __restrict__ x,
                            const float* __restrict__ kr, const float* __restrict__ ki,
                            const float* __restrict__ vr, const float* __restrict__ vi) {
    int b = blockIdx.x, t = threadIdx.x;
    if (b < 2048) {
        size_t base = (size_t)b * 16384;
        const float4* src = (const float4*)(x + base);
        #pragma unroll
        for (int i = 0; i < 16; i++) {
            float4 v = src[t + i * 256];
            __nv_bfloat162 p0 = __float22bfloat162_rn(make_float2(v.x, v.y));
            __nv_bfloat162 p1 = __float22bfloat162_rn(make_float2(v.z, v.w));
            uint2 q = make_uint2(*(uint32_t*)&p0, *(uint32_t*)&p1);
            *(uint2*)(g_Xbf + base + (size_t)(t + i * 256) * 4) = q;
        }
    } else if (b < 3072) {
        int h = b - 2048;
        const float* src = (h < 512) ? (vr + h) : (vi + (h - 512));
        float sum = 0.0f;
        for (int m = t; m < 512; m += 256) {
            float v = src[(size_t)m * 512];
            g_VT[(size_t)h * 512 + m] = __float2bfloat16(v);
            sum += v;
        }
        __shared__ float red[8];
        #pragma unroll
        for (int o = 16; o; o >>= 1) sum += __shfl_xor_sync(0xffffffffu, sum, o);
        if ((t & 31) == 0) red[t >> 5] = sum;
        __syncthreads();
        if (t == 0) {
            float s = 0.0f;
            #pragma unroll
            for (int i = 0; i < 8; i++) s += red[i];
            g_vbar[h] = s * (1.0f / 512.0f);
        }
    } else {
        int m = b - 3072;
        for (int c = t; c < 1024; c += 256) {
            float v = (c < 512) ? kr[(size_t)m * 512 + c] : ki[(size_t)m * 512 + c - 512];
            g_Kbf[(size_t)m * 1024 + c] = __float2bfloat16(v);
        }
    }
}

// ============================================================================
// Unified GEMM: C[64 x 512] tile = A[64 x K] * B[512 x K]^T, K-chunked by 64.
//  MODE 0: A=g_Xbf (K=1024), B=g_Kbf, epilogue softmax -> g_d
//  MODE 1: A=g_d (K=512),  B=g_VT+n_base*512, epilogue +vbar -> out
//  256 threads = 8 warps in 2(M) x 4(N); warp tile 32 x 128.
// ============================================================================
template <int MODE>
__global__ void __launch_bounds__(256, 1) gemm_kernel(float* __restrict__ outp) {
    constexpr int NC      = (MODE == 0) ? 16 : 8;     // K chunks of 64
    constexpr int ASTRIDE = (MODE == 0) ? 1024 : 512; // elements
    constexpr int BSTRIDE = (MODE == 0) ? 1024 : 512;

    extern __shared__ char S[];
    const uint32_t sb = smem_u32(S);
    const uint32_t abase[2] = { sb, sb + 8192 };
    const uint32_t bbase[2] = { sb + 16384, sb + 16384 + 65536 };

    const int tid = threadIdx.x, lid = tid & 31, w = tid >> 5;
    const int wm = w >> 2, wn = w & 3;            // warp grid 2 x 4
    const int bm0 = blockIdx.x * 64;
    const int n_base = (MODE == 1) ? (int)blockIdx.y * 512 : 0;

    const __nv_bfloat16* Asrc = (MODE == 0) ? (g_Xbf + (size_t)bm0 * 1024)
                                            : (g_d   + (size_t)bm0 * 512);
    const __nv_bfloat16* Bsrc = (MODE == 0) ? g_Kbf : (g_VT + (size_t)n_base * 512);

    // ---- async chunk loader (one commit group per chunk) ----
    auto load_chunk = [&](int c) {
        const int s = c & 1, kc = c * 64;
        #pragma unroll
        for (int it = 0; it < 2; it++) {                 // A: 64 rows x 8 segs
            int u = tid + it * 256, row = u >> 3, seg = u & 7;
            const char* src = (const char*)(Asrc + (size_t)row * ASTRIDE + kc + seg * 8);
            CP_ASYNC16(abase[s] + SWZ((uint32_t)(row * 128 + seg * 16)), src);
        }
        #pragma unroll
        for (int it = 0; it < 16; it++) {                // B: 512 rows x 8 segs
            int u = tid + it * 256, row = u >> 3, seg = u & 7;
            const char* src = (const char*)(Bsrc + (size_t)row * BSTRIDE + kc + seg * 8);
            CP_ASYNC16(bbase[s] + SWZ((uint32_t)(row * 128 + seg * 16)), src);
        }
        CP_COMMIT();
    };

    // ---- per-thread ldmatrix byte offsets (pre-swizzle) ----
    uint32_t aoff[2], boff[8];
    #pragma unroll
    for (int mi = 0; mi < 2; mi++)
        aoff[mi] = (uint32_t)((wm * 32 + mi * 16 + (lid & 15)) * 128 + (lid >> 4) * 16);
    #pragma unroll
    for (int g = 0; g < 8; g++)
        boff[g] = (uint32_t)((wn * 128 + g * 16 + (lid & 15)) * 128 + (lid >> 4) * 16);

    float acc[2][16][4];
    #pragma unroll
    for (int mi = 0; mi < 2; mi++)
        #pragma unroll
        for (int nf = 0; nf < 16; nf++)
            #pragma unroll
            for (int j = 0; j < 4; j++) acc[mi][nf][j] = 0.0f;

    auto compute = [&](int s) {
        const uint32_t ab = abase[s], bb = bbase[s];
        #pragma unroll
        for (int ks = 0; ks < 4; ks++) {
            uint32_t a[2][4];
            #pragma unroll
            for (int mi = 0; mi < 2; mi++) LDSM_X4(a[mi], ab + SWZ(aoff[mi] + ks * 32));
            #pragma unroll
            for (int g = 0; g < 8; g++) {
                uint32_t bfrag[4];
                LDSM_X4(bfrag, bb + SWZ(boff[g] + ks * 32));
                #pragma unroll
                for (int mi = 0; mi < 2; mi++) {
                    mma16816(acc[mi][2 * g],     a[mi], bfrag[0], bfrag[2]);
                    mma16816(acc[mi][2 * g + 1], a[mi], bfrag[1], bfrag[3]);
                }
            }
        }
    };

    // ---- mainloop: double-buffered ----
    load_chunk(0);
    for (int c = 0; c < NC; c++) {
        if (c + 1 < NC) { load_chunk(c + 1); CP_WAIT1(); }
        else            { CP_WAIT0(); }
        __syncthreads();
        compute(c & 1);
        __syncthreads();
    }

    // ---- epilogue ----
    if (MODE == 0) {
        // softmax over the full 512-wide row held across the 4 N-warps
        float* red = (float*)S;   // 64 rows x 4 warps fp32 (1 KB), buffers are free now
        #pragma unroll
        for (int mi = 0; mi < 2; mi++)
            #pragma unroll
            for (int nf = 0; nf < 16; nf++)
                #pragma unroll
                for (int j = 0; j < 4; j++)
                    acc[mi][nf][j] = __expf(acc[mi][nf][j] * TEMPERATURE);

        #pragma unroll
        for (int mi = 0; mi < 2; mi++) {
            float sA = 0.0f, sB = 0.0f;
            #pragma unroll
            for (int nf = 0; nf < 16; nf++) {
                sA += acc[mi][nf][0] + acc[mi][nf][1];
                sB += acc[mi][nf][2] + acc[mi][nf][3];
            }
            sA += __shfl_xor_sync(0xffffffffu, sA, 1);
            sA += __shfl_xor_sync(0xffffffffu, sA, 2);
            sB += __shfl_xor_sync(0xffffffffu, sB, 1);
            sB += __shfl_xor_sync(0xffffffffu, sB, 2);
            if ((lid & 3) == 0) {
                int r = wm * 32 + mi * 16 + (lid >> 2);
                red[r * 4 + wn]       = sA;
                red[(r + 8) * 4 + wn] = sB;
            }
        }
        __syncthreads();

        #pragma unroll
        for (int mi = 0; mi < 2; mi++) {
            int rA = wm * 32 + mi * 16 + (lid >> 2), rB = rA + 8;
            float rinvA = 1.0f / (red[rA * 4] + red[rA * 4 + 1] + red[rA * 4 + 2] + red[rA * 4 + 3]);
            float rinvB = 1.0f / (red[rB * 4] + red[rB * 4 + 1] + red[rB * 4 + 2] + red[rB * 4 + 3]);
            size_t baseA = (size_t)(bm0 + rA) * 512, baseB = (size_t)(bm0 + rB) * 512;
            #pragma unroll
            for (int nf = 0; nf < 16; nf++) {
                int gc = wn * 128 + nf * 8 + 2 * (lid & 3);
                __nv_bfloat162 pA = __float22bfloat162_rn(make_float2(
                    acc[mi][nf][0] * rinvA - INV512, acc[mi][nf][1] * rinvA - INV512));
                __nv_bfloat162 pB = __float22bfloat162_rn(make_float2(
                    acc[mi][nf][2] * rinvB - INV512, acc[mi][nf][3] * rinvB - INV512));
                *(uint32_t*)(g_d + baseA + gc) = *(uint32_t*)&pA;
                *(uint32_t*)(g_d + baseB + gc) = *(uint32_t*)&pB;
            }
        }
    } else {
        #pragma unroll
        for (int mi = 0; mi < 2; mi++) {
            int r = wm * 32 + mi * 16 + (lid >> 2);
            size_t rowA = (size_t)(bm0 + r) * 1024, rowB = (size_t)(bm0 + r + 8) * 1024;
            #pragma unroll
            for (int nf = 0; nf < 16; nf++) {
                int gc = n_base + wn * 128 + nf * 8 + 2 * (lid & 3);
                float2 vb = *(const float2*)(g_vbar + gc);
                float2 o0 = make_float2(acc[mi][nf][0] + vb.x, acc[mi][nf][1] + vb.y);
                float2 o1 = make_float2(acc[mi][nf][2] + vb.x, acc[mi][nf][3] + vb.y);
                *(float2*)(outp + rowA + gc) = o0;
                *(float2*)(outp + rowB + gc) = o1;
            }
        }
    }
}

// ============================================================================
extern "C" void kernel_launch(void* const* d_in, const int* in_sizes, int n_in,
                              void* d_out, int out_size) {
    (void)in_sizes; (void)n_in; (void)out_size;
    const float* x  = (const float*)d_in[0];
    const float* kr = (const float*)d_in[1];
    const float* ki = (const float*)d_in[2];
    const float* vr = (const float*)d_in[3];
    const float* vi = (const float*)d_in[4];
    float* out = (float*)d_out;

    cudaFuncSetAttribute(gemm_kernel<0>, cudaFuncAttributeMaxDynamicSharedMemorySize, SMEM_BYTES);
    cudaFuncSetAttribute(gemm_kernel<1>, cudaFuncAttributeMaxDynamicSharedMemorySize, SMEM_BYTES);

    prep_kernel<<<3584, 256>>>(x, kr, ki, vr, vi);
    gemm_kernel<0><<<512, 256, SMEM_BYTES>>>(nullptr);
    gemm_kernel<1><<<dim3(512, 2), 256, SMEM_BYTES>>>(out);
}

// round 5
// speedup vs baseline: 1.0374x; 1.0374x over previous
#include <cuda_runtime.h>
#include <cuda_bf16.h>
#include <cstdint>
#include <cstddef>

// ============================================================================
// HolographicMemory on GB300 (base-sm_103 path): HMMA mma.sync + ldmatrix +
// 3-stage cp.async pipeline.
//
//   prep : g_Xbf = bf16(x); g_Kbf[512x1024] = bf16([kr|ki]);
//          g_VT[1024x512] = bf16(V^T); g_vbar[1024] = colmean(V) fp32
//   G1   : energy = Xbf * Kbf^T ; softmax; g_d = attn - 1/512 (bf16)
//   G2   : out = vbar + g_d * V   (B = VT)
// ============================================================================

#define TEMPERATURE 0.04419417382415922f   // 1/sqrt(512)
#define INV512      0.001953125f

// ---------------- device scratch (no allocation allowed) --------------------
__device__ __nv_bfloat16 g_Xbf[(size_t)32768 * 1024];
__device__ __nv_bfloat16 g_Kbf[512 * 1024];
__device__ __nv_bfloat16 g_VT[1024 * 512];
__device__ float         g_vbar[1024];
__device__ __nv_bfloat16 g_d[(size_t)32768 * 512];

// ---------------- helpers ---------------------------------------------------
__device__ __forceinline__ uint32_t smem_u32(const void* p) {
    uint32_t a;
    asm("{ .reg .u64 t; cvta.to.shared.u64 t, %1; cvt.u32.u64 %0, t; }" : "=r"(a) : "l"(p));
    return a;
}
__device__ __forceinline__ uint32_t SWZ(uint32_t x) { return x ^ ((x >> 3) & 0x70); }

#define CP_ASYNC16(dst_u32, src_ptr) \
    asm volatile("cp.async.cg.shared.global [%0], [%1], 16;" :: "r"(dst_u32), "l"(src_ptr) : "memory")
#define CP_COMMIT() asm volatile("cp.async.commit_group;" ::: "memory")
#define CP_WAIT1()  asm volatile("cp.async.wait_group 1;" ::: "memory")
#define CP_WAIT0()  asm volatile("cp.async.wait_group 0;" ::: "memory")

#define LDSM_X4(R, addr) \
    asm volatile("ldmatrix.sync.aligned.m8n8.x4.shared.b16 {%0,%1,%2,%3}, [%4];" \
        : "=r"((R)[0]), "=r"((R)[1]), "=r"((R)[2]), "=r"((R)[3]) : "r"(addr))

__device__ __forceinline__ void mma16816(float* c, const uint32_t* a, uint32_t b0, uint32_t b1) {
    asm volatile(
        "mma.sync.aligned.m16n8k16.row.col.f32.bf16.bf16.f32 "
        "{%0,%1,%2,%3}, {%4,%5,%6,%7}, {%8,%9}, {%0,%1,%2,%3};"
        : "+f"(c[0]), "+f"(c[1]), "+f"(c[2]), "+f"(c[3])
        : "r"(a[0]), "r"(a[1]), "r"(a[2]), "r"(a[3]), "r"(b0), "r"(b1));
}

// ---------------- smem layout: 3 pipeline stages ----------------------------
// Stage = A[64x64 bf16]=8KB + B[512x64 bf16]=64KB.
static constexpr int NSTAGE    = 3;
static constexpr int A_STAGE   = 8192;
static constexpr int B_STAGE   = 65536;
static constexpr int B_BASE    = NSTAGE * A_STAGE;               // 24576
static constexpr int SMEM_BYTES = NSTAGE * (A_STAGE + B_STAGE);  // 221184

// ============================================================================
// prep kernel: grid 3584 x 256
// ============================================================================
__global__ void prep_kernel(const float* __restrict__ x,
                            const float* __restrict__ kr, const float* __restrict__ ki,
                            const float* __restrict__ vr, const float* __restrict__ vi) {
    int b = blockIdx.x, t = threadIdx.x;
    if (b < 2048) {
        size_t base = (size_t)b * 16384;
        const float4* src = (const float4*)(x + base);
        #pragma unroll
        for (int i = 0; i < 16; i++) {
            float4 v = src[t + i * 256];
            __nv_bfloat162 p0 = __float22bfloat162_rn(make_float2(v.x, v.y));
            __nv_bfloat162 p1 = __float22bfloat162_rn(make_float2(v.z, v.w));
            uint2 q = make_uint2(*(uint32_t*)&p0, *(uint32_t*)&p1);
            *(uint2*)(g_Xbf + base + (size_t)(t + i * 256) * 4) = q;
        }
    } else if (b < 3072) {
        int h = b - 2048;
        const float* src = (h < 512) ? (vr + h) : (vi + (h - 512));
        float sum = 0.0f;
        for (int m = t; m < 512; m += 256) {
            float v = src[(size_t)m * 512];
            g_VT[(size_t)h * 512 + m] = __float2bfloat16(v);
            sum += v;
        }
        __shared__ float red[8];
        #pragma unroll
        for (int o = 16; o; o >>= 1) sum += __shfl_xor_sync(0xffffffffu, sum, o);
        if ((t & 31) == 0) red[t >> 5] = sum;
        __syncthreads();
        if (t == 0) {
            float s = 0.0f;
            #pragma unroll
            for (int i = 0; i < 8; i++) s += red[i];
            g_vbar[h] = s * (1.0f / 512.0f);
        }
    } else {
        int m = b - 3072;
        for (int c = t; c < 1024; c += 256) {
            float v = (c < 512) ? kr[(size_t)m * 512 + c] : ki[(size_t)m * 512 + c - 512];
            g_Kbf[(size_t)m * 1024 + c] = __float2bfloat16(v);
        }
    }
}

// ============================================================================
// Unified GEMM: C[64 x 512] = A[64 x K] * B[512 x K]^T, K-chunked by 64.
//  MODE 0: A=g_Xbf (K=1024), B=g_Kbf, epilogue softmax -> g_d
//  MODE 1: A=g_d (K=512),  B=g_VT+n_base*512, epilogue +vbar -> out
//  256 threads = 8 warps in 2(M) x 4(N); warp tile 32 x 128.
//  3-stage cp.async pipeline, one __syncthreads per chunk.
// ============================================================================
template <int MODE>
__global__ void __launch_bounds__(256, 1) gemm_kernel(float* __restrict__ outp) {
    constexpr int NC      = (MODE == 0) ? 16 : 8;     // K chunks of 64
    constexpr int ASTRIDE = (MODE == 0) ? 1024 : 512; // elements
    constexpr int BSTRIDE = (MODE == 0) ? 1024 : 512;

    extern __shared__ char S[];
    const uint32_t sb = smem_u32(S);

    const int tid = threadIdx.x, lid = tid & 31, w = tid >> 5;
    const int wm = w >> 2, wn = w & 3;            // warp grid 2 x 4
    const int bm0 = blockIdx.x * 64;
    const int n_base = (MODE == 1) ? (int)blockIdx.y * 512 : 0;

    const __nv_bfloat16* Asrc = (MODE == 0) ? (g_Xbf + (size_t)bm0 * 1024)
                                            : (g_d   + (size_t)bm0 * 512);
    const __nv_bfloat16* Bsrc = (MODE == 0) ? g_Kbf : (g_VT + (size_t)n_base * 512);

    // ---- async chunk loader into stage st (one commit group per chunk) ----
    auto load_chunk = [&](int c, int st) {
        const int kc = c * 64;
        const uint32_t ab = sb + st * A_STAGE;
        const uint32_t bb = sb + B_BASE + st * B_STAGE;
        #pragma unroll
        for (int it = 0; it < 2; it++) {                 // A: 64 rows x 8 segs
            int u = tid + it * 256, row = u >> 3, seg = u & 7;
            const char* src = (const char*)(Asrc + (size_t)row * ASTRIDE + kc + seg * 8);
            CP_ASYNC16(ab + SWZ((uint32_t)(row * 128 + seg * 16)), src);
        }
        #pragma unroll
        for (int it = 0; it < 16; it++) {                // B: 512 rows x 8 segs
            int u = tid + it * 256, row = u >> 3, seg = u & 7;
            const char* src = (const char*)(Bsrc + (size_t)row * BSTRIDE + kc + seg * 8);
            CP_ASYNC16(bb + SWZ((uint32_t)(row * 128 + seg * 16)), src);
        }
        CP_COMMIT();
    };

    // ---- per-thread ldmatrix byte offsets (pre-swizzle) ----
    uint32_t aoff[2], boff[8];
    #pragma unroll
    for (int mi = 0; mi < 2; mi++)
        aoff[mi] = (uint32_t)((wm * 32 + mi * 16 + (lid & 15)) * 128 + (lid >> 4) * 16);
    #pragma unroll
    for (int g = 0; g < 8; g++)
        boff[g] = (uint32_t)((wn * 128 + g * 16 + (lid & 15)) * 128 + (lid >> 4) * 16);

    float acc[2][16][4];
    #pragma unroll
    for (int mi = 0; mi < 2; mi++)
        #pragma unroll
        for (int nf = 0; nf < 16; nf++)
            #pragma unroll
            for (int j = 0; j < 4; j++) acc[mi][nf][j] = 0.0f;

    auto compute = [&](int st) {
        const uint32_t ab = sb + st * A_STAGE;
        const uint32_t bb = sb + B_BASE + st * B_STAGE;
        #pragma unroll
        for (int ks = 0; ks < 4; ks++) {
            uint32_t a[2][4];
            #pragma unroll
            for (int mi = 0; mi < 2; mi++) LDSM_X4(a[mi], ab + SWZ(aoff[mi] + ks * 32));
            #pragma unroll
            for (int g = 0; g < 8; g++) {
                uint32_t bfrag[4];
                LDSM_X4(bfrag, bb + SWZ(boff[g] + ks * 32));
                #pragma unroll
                for (int mi = 0; mi < 2; mi++) {
                    mma16816(acc[mi][2 * g],     a[mi], bfrag[0], bfrag[2]);
                    mma16816(acc[mi][2 * g + 1], a[mi], bfrag[1], bfrag[3]);
                }
            }
        }
    };

    // ---- mainloop: 3-stage pipeline, prefetch distance 2 ----
    load_chunk(0, 0);
    load_chunk(1, 1);
    #pragma unroll 1
    for (int c = 0; c < NC; c++) {
        if (c < NC - 1) { CP_WAIT1(); } else { CP_WAIT0(); }
        __syncthreads();                      // chunk c visible to all warps;
                                              // all warps done computing c-1
        if (c + 2 < NC) load_chunk(c + 2, (c + 2) % NSTAGE);
        compute(c % NSTAGE);
    }
    __syncthreads();   // last compute reads smem that epilogue reuses

    // ---- epilogue ----
    if (MODE == 0) {
        // softmax over the full 512-wide row held across the 4 N-warps
        float* red = (float*)S;   // 1 KB scratch in stage-0 A buffer
        #pragma unroll
        for (int mi = 0; mi < 2; mi++)
            #pragma unroll
            for (int nf = 0; nf < 16; nf++)
                #pragma unroll
                for (int j = 0; j < 4; j++)
                    acc[mi][nf][j] = __expf(acc[mi][nf][j] * TEMPERATURE);

        #pragma unroll
        for (int mi = 0; mi < 2; mi++) {
            float sA = 0.0f, sB = 0.0f;
            #pragma unroll
            for (int nf = 0; nf < 16; nf++) {
                sA += acc[mi][nf][0] + acc[mi][nf][1];
                sB += acc[mi][nf][2] + acc[mi][nf][3];
            }
            sA += __shfl_xor_sync(0xffffffffu, sA, 1);
            sA += __shfl_xor_sync(0xffffffffu, sA, 2);
            sB += __shfl_xor_sync(0xffffffffu, sB, 1);
            sB += __shfl_xor_sync(0xffffffffu, sB, 2);
            if ((lid & 3) == 0) {
                int r = wm * 32 + mi * 16 + (lid >> 2);
                red[r * 4 + wn]       = sA;
                red[(r + 8) * 4 + wn] = sB;
            }
        }
        __syncthreads();

        #pragma unroll
        for (int mi = 0; mi < 2; mi++) {
            int rA = wm * 32 + mi * 16 + (lid >> 2), rB = rA + 8;
            float rinvA = 1.0f / (red[rA * 4] + red[rA * 4 + 1] + red[rA * 4 + 2] + red[rA * 4 + 3]);
            float rinvB = 1.0f / (red[rB * 4] + red[rB * 4 + 1] + red[rB * 4 + 2] + red[rB * 4 + 3]);
            size_t baseA = (size_t)(bm0 + rA) * 512, baseB = (size_t)(bm0 + rB) * 512;
            #pragma unroll
            for (int nf = 0; nf < 16; nf++) {
                int gc = wn * 128 + nf * 8 + 2 * (lid & 3);
                __nv_bfloat162 pA = __float22bfloat162_rn(make_float2(
                    acc[mi][nf][0] * rinvA - INV512, acc[mi][nf][1] * rinvA - INV512));
                __nv_bfloat162 pB = __float22bfloat162_rn(make_float2(
                    acc[mi][nf][2] * rinvB - INV512, acc[mi][nf][3] * rinvB - INV512));
                *(uint32_t*)(g_d + baseA + gc) = *(uint32_t*)&pA;
                *(uint32_t*)(g_d + baseB + gc) = *(uint32_t*)&pB;
            }
        }
    } else {
        #pragma unroll
        for (int mi = 0; mi < 2; mi++) {
            int r = wm * 32 + mi * 16 + (lid >> 2);
            size_t rowA = (size_t)(bm0 + r) * 1024, rowB = (size_t)(bm0 + r + 8) * 1024;
            #pragma unroll
            for (int nf = 0; nf < 16; nf++) {
                int gc = n_base + wn * 128 + nf * 8 + 2 * (lid & 3);
                float2 vb = *(const float2*)(g_vbar + gc);
                float2 o0 = make_float2(acc[mi][nf][0] + vb.x, acc[mi][nf][1] + vb.y);
                float2 o1 = make_float2(acc[mi][nf][2] + vb.x, acc[mi][nf][3] + vb.y);
                *(float2*)(outp + rowA + gc) = o0;
                *(float2*)(outp + rowB + gc) = o1;
            }
        }
    }
}

// ============================================================================
extern "C" void kernel_launch(void* const* d_in, const int* in_sizes, int n_in,
                              void* d_out, int out_size) {
    (void)in_sizes; (void)n_in; (void)out_size;
    const float* x  = (const float*)d_in[0];
    const float* kr = (const float*)d_in[1];
    const float* ki = (const float*)d_in[2];
    const float* vr = (const float*)d_in[3];
    const float* vi = (const float*)d_in[4];
    float* out = (float*)d_out;

    cudaFuncSetAttribute(gemm_kernel<0>, cudaFuncAttributeMaxDynamicSharedMemorySize, SMEM_BYTES);
    cudaFuncSetAttribute(gemm_kernel<1>, cudaFuncAttributeMaxDynamicSharedMemorySize, SMEM_BYTES);

    prep_kernel<<<3584, 256>>>(x, kr, ki, vr, vi);
    gemm_kernel<0><<<512, 256, SMEM_BYTES>>>(nullptr);
    gemm_kernel<1><<<dim3(512, 2), 256, SMEM_BYTES>>>(out);
}

// round 10
// speedup vs baseline: 1.0514x; 1.0135x over previous
#include <cuda_runtime.h>
#include <cuda_fp16.h>
#include <cstdint>
#include <cstddef>

// ============================================================================
// HolographicMemory on GB300 (base-sm_103 path): fp16 HMMA (f16 accum) +
// ldmatrix + 3-stage cp.async pipeline.
//
//   prep : g_Xh = fp16(x); g_Kh[512x1024] = fp16([kr|ki]);
//          g_VT[1024x512] = fp16(V^T); g_vbar[1024] = colmean(V) fp32
//   G1   : energy = Xh * Kh^T (f16 acc); softmax; g_d = 512*attn - 1 (fp16)
//   G2   : out = vbar + (g_d * V) / 512   (B = VT, f16 acc)
// ============================================================================

#define TEMPERATURE 0.04419417382415922f   // 1/sqrt(512)

// ---------------- device scratch (no allocation allowed) --------------------
__device__ __half g_Xh[(size_t)32768 * 1024];
__device__ __half g_Kh[512 * 1024];
__device__ __half g_VT[1024 * 512];
__device__ float  g_vbar[1024];
__device__ __half g_d[(size_t)32768 * 512];

// ---------------- helpers ---------------------------------------------------
__device__ __forceinline__ uint32_t smem_u32(const void* p) {
    uint32_t a;
    asm("{ .reg .u64 t; cvta.to.shared.u64 t, %1; cvt.u32.u64 %0, t; }" : "=r"(a) : "l"(p));
    return a;
}
__device__ __forceinline__ uint32_t SWZ(uint32_t x) { return x ^ ((x >> 3) & 0x70); }

#define CP_ASYNC16(dst_u32, src_ptr) \
    asm volatile("cp.async.cg.shared.global [%0], [%1], 16;" :: "r"(dst_u32), "l"(src_ptr) : "memory")
#define CP_COMMIT() asm volatile("cp.async.commit_group;" ::: "memory")
#define CP_WAIT1()  asm volatile("cp.async.wait_group 1;" ::: "memory")
#define CP_WAIT0()  asm volatile("cp.async.wait_group 0;" ::: "memory")

#define LDSM_X4(R, addr) \
    asm volatile("ldmatrix.sync.aligned.m8n8.x4.shared.b16 {%0,%1,%2,%3}, [%4];" \
        : "=r"((R)[0]), "=r"((R)[1]), "=r"((R)[2]), "=r"((R)[3]) : "r"(addr))

// m16n8k16 fp16 inputs, fp16 accumulators (2 packed regs)
__device__ __forceinline__ void mma16816h(uint32_t* c, const uint32_t* a, uint32_t b0, uint32_t b1) {
    asm volatile(
        "mma.sync.aligned.m16n8k16.row.col.f16.f16.f16.f16 "
        "{%0,%1}, {%2,%3,%4,%5}, {%6,%7}, {%0,%1};"
        : "+r"(c[0]), "+r"(c[1])
        : "r"(a[0]), "r"(a[1]), "r"(a[2]), "r"(a[3]), "r"(b0), "r"(b1));
}

// ---------------- smem layout: 3 pipeline stages ----------------------------
static constexpr int NSTAGE    = 3;
static constexpr int A_STAGE   = 8192;    // 64 x 64 fp16
static constexpr int B_STAGE   = 65536;   // 512 x 64 fp16
static constexpr int B_BASE    = NSTAGE * A_STAGE;
static constexpr int SMEM_BYTES = NSTAGE * (A_STAGE + B_STAGE);  // 221184

// ============================================================================
// prep kernel: grid 3584 x 256
// ============================================================================
__global__ void prep_kernel(const float* __restrict__ x,
                            const float* __restrict__ kr, const float* __restrict__ ki,
                            const float* __restrict__ vr, const float* __restrict__ vi) {
    int b = blockIdx.x, t = threadIdx.x;
    if (b < 2048) {
        size_t base = (size_t)b * 16384;
        const float4* src = (const float4*)(x + base);
        #pragma unroll
        for (int i = 0; i < 16; i++) {
            float4 v = src[t + i * 256];
            __half2 p0 = __float22half2_rn(make_float2(v.x, v.y));
            __half2 p1 = __float22half2_rn(make_float2(v.z, v.w));
            uint2 q = make_uint2(*(uint32_t*)&p0, *(uint32_t*)&p1);
            *(uint2*)(g_Xh + base + (size_t)(t + i * 256) * 4) = q;
        }
    } else if (b < 3072) {
        int h = b - 2048;
        const float* src = (h < 512) ? (vr + h) : (vi + (h - 512));
        float sum = 0.0f;
        for (int m = t; m < 512; m += 256) {
            float v = src[(size_t)m * 512];
            g_VT[(size_t)h * 512 + m] = __float2half(v);
            sum += v;
        }
        __shared__ float red[8];
        #pragma unroll
        for (int o = 16; o; o >>= 1) sum += __shfl_xor_sync(0xffffffffu, sum, o);
        if ((t & 31) == 0) red[t >> 5] = sum;
        __syncthreads();
        if (t == 0) {
            float s = 0.0f;
            #pragma unroll
            for (int i = 0; i < 8; i++) s += red[i];
            g_vbar[h] = s * (1.0f / 512.0f);
        }
    } else {
        int m = b - 3072;
        for (int c = t; c < 1024; c += 256) {
            float v = (c < 512) ? kr[(size_t)m * 512 + c] : ki[(size_t)m * 512 + c - 512];
            g_Kh[(size_t)m * 1024 + c] = __float2half(v);
        }
    }
}

// ============================================================================
// Unified GEMM: C[64 x 512] = A[64 x K] * B[512 x K]^T, K-chunked by 64.
//  MODE 0: A=g_Xh (K=1024), B=g_Kh, epilogue softmax -> g_d (d' = 512*attn-1)
//  MODE 1: A=g_d (K=512),  B=g_VT+n_base*512, epilogue vbar + acc/512 -> out
//  256 threads = 8 warps in 2(M) x 4(N); warp tile 32 x 128; f16 accumulators.
// ============================================================================
template <int MODE>
__global__ void __launch_bounds__(256, 1) gemm_kernel(float* __restrict__ outp) {
    constexpr int NC      = (MODE == 0) ? 16 : 8;
    constexpr int ASTRIDE = (MODE == 0) ? 1024 : 512;
    constexpr int BSTRIDE = (MODE == 0) ? 1024 : 512;

    extern __shared__ char S[];
    const uint32_t sb = smem_u32(S);

    const int tid = threadIdx.x, lid = tid & 31, w = tid >> 5;
    const int wm = w >> 2, wn = w & 3;
    const int bm0 = blockIdx.x * 64;
    const int n_base = (MODE == 1) ? (int)blockIdx.y * 512 : 0;

    const __half* Asrc = (MODE == 0) ? (g_Xh + (size_t)bm0 * 1024)
                                     : (g_d  + (size_t)bm0 * 512);
    const __half* Bsrc = (MODE == 0) ? g_Kh : (g_VT + (size_t)n_base * 512);

    auto load_chunk = [&](int c, int st) {
        const int kc = c * 64;
        const uint32_t ab = sb + st * A_STAGE;
        const uint32_t bb = sb + B_BASE + st * B_STAGE;
        #pragma unroll
        for (int it = 0; it < 2; it++) {
            int u = tid + it * 256, row = u >> 3, seg = u & 7;
            const char* src = (const char*)(Asrc + (size_t)row * ASTRIDE + kc + seg * 8);
            CP_ASYNC16(ab + SWZ((uint32_t)(row * 128 + seg * 16)), src);
        }
        #pragma unroll
        for (int it = 0; it < 16; it++) {
            int u = tid + it * 256, row = u >> 3, seg = u & 7;
            const char* src = (const char*)(Bsrc + (size_t)row * BSTRIDE + kc + seg * 8);
            CP_ASYNC16(bb + SWZ((uint32_t)(row * 128 + seg * 16)), src);
        }
        CP_COMMIT();
    };

    uint32_t aoff[2], boff[8];
    #pragma unroll
    for (int mi = 0; mi < 2; mi++)
        aoff[mi] = (uint32_t)((wm * 32 + mi * 16 + (lid & 15)) * 128 + (lid >> 4) * 16);
    #pragma unroll
    for (int g = 0; g < 8; g++)
        boff[g] = (uint32_t)((wn * 128 + g * 16 + (lid & 15)) * 128 + (lid >> 4) * 16);

    // f16 accumulators: [mi][nf] -> 2 packed regs {c0,c1},{c2,c3}
    uint32_t hacc[2][16][2];
    #pragma unroll
    for (int mi = 0; mi < 2; mi++)
        #pragma unroll
        for (int nf = 0; nf < 16; nf++)
            hacc[mi][nf][0] = hacc[mi][nf][1] = 0u;

    auto compute = [&](int st) {
        const uint32_t ab = sb + st * A_STAGE;
        const uint32_t bb = sb + B_BASE + st * B_STAGE;
        #pragma unroll
        for (int ks = 0; ks < 4; ks++) {
            uint32_t a[2][4];
            #pragma unroll
            for (int mi = 0; mi < 2; mi++) LDSM_X4(a[mi], ab + SWZ(aoff[mi] + ks * 32));
            #pragma unroll
            for (int g = 0; g < 8; g++) {
                uint32_t bfrag[4];
                LDSM_X4(bfrag, bb + SWZ(boff[g] + ks * 32));
                #pragma unroll
                for (int mi = 0; mi < 2; mi++) {
                    mma16816h(hacc[mi][2 * g],     a[mi], bfrag[0], bfrag[2]);
                    mma16816h(hacc[mi][2 * g + 1], a[mi], bfrag[1], bfrag[3]);
                }
            }
        }
    };

    load_chunk(0, 0);
    load_chunk(1, 1);
    #pragma unroll 1
    for (int c = 0; c < NC; c++) {
        if (c < NC - 1) { CP_WAIT1(); } else { CP_WAIT0(); }
        __syncthreads();
        if (c + 2 < NC) load_chunk(c + 2, (c + 2) % NSTAGE);
        compute(c % NSTAGE);
    }
    __syncthreads();

    // ---- expand f16 accumulators to fp32 ----
    float acc[2][16][4];
    #pragma unroll
    for (int mi = 0; mi < 2; mi++)
        #pragma unroll
        for (int nf = 0; nf < 16; nf++) {
            float2 lo = __half22float2(*(__half2*)&hacc[mi][nf][0]);
            float2 hi = __half22float2(*(__half2*)&hacc[mi][nf][1]);
            acc[mi][nf][0] = lo.x; acc[mi][nf][1] = lo.y;
            acc[mi][nf][2] = hi.x; acc[mi][nf][3] = hi.y;
        }

    // ---- epilogue ----
    if (MODE == 0) {
        float* red = (float*)S;
        #pragma unroll
        for (int mi = 0; mi < 2; mi++)
            #pragma unroll
            for (int nf = 0; nf < 16; nf++)
                #pragma unroll
                for (int j = 0; j < 4; j++)
                    acc[mi][nf][j] = __expf(acc[mi][nf][j] * TEMPERATURE);

        #pragma unroll
        for (int mi = 0; mi < 2; mi++) {
            float sA = 0.0f, sB = 0.0f;
            #pragma unroll
            for (int nf = 0; nf < 16; nf++) {
                sA += acc[mi][nf][0] + acc[mi][nf][1];
                sB += acc[mi][nf][2] + acc[mi][nf][3];
            }
            sA += __shfl_xor_sync(0xffffffffu, sA, 1);
            sA += __shfl_xor_sync(0xffffffffu, sA, 2);
            sB += __shfl_xor_sync(0xffffffffu, sB, 1);
            sB += __shfl_xor_sync(0xffffffffu, sB, 2);
            if ((lid & 3) == 0) {
                int r = wm * 32 + mi * 16 + (lid >> 2);
                red[r * 4 + wn]       = sA;
                red[(r + 8) * 4 + wn] = sB;
            }
        }
        __syncthreads();

        #pragma unroll
        for (int mi = 0; mi < 2; mi++) {
            int rA = wm * 32 + mi * 16 + (lid >> 2), rB = rA + 8;
            // scale = 512 / sum  ->  d' = exp*scale - 1
            float scA = 512.0f / (red[rA * 4] + red[rA * 4 + 1] + red[rA * 4 + 2] + red[rA * 4 + 3]);
            float scB = 512.0f / (red[rB * 4] + red[rB * 4 + 1] + red[rB * 4 + 2] + red[rB * 4 + 3]);
            size_t baseA = (size_t)(bm0 + rA) * 512, baseB = (size_t)(bm0 + rB) * 512;
            #pragma unroll
            for (int nf = 0; nf < 16; nf++) {
                int gc = wn * 128 + nf * 8 + 2 * (lid & 3);
                __half2 pA = __float22half2_rn(make_float2(
                    acc[mi][nf][0] * scA - 1.0f, acc[mi][nf][1] * scA - 1.0f));
                __half2 pB = __float22half2_rn(make_float2(
                    acc[mi][nf][2] * scB - 1.0f, acc[mi][nf][3] * scB - 1.0f));
                *(uint32_t*)(g_d + baseA + gc) = *(uint32_t*)&pA;
                *(uint32_t*)(g_d + baseB + gc) = *(uint32_t*)&pB;
            }
        }
    } else {
        #pragma unroll
        for (int mi = 0; mi < 2; mi++) {
            int r = wm * 32 + mi * 16 + (lid >> 2);
            size_t rowA = (size_t)(bm0 + r) * 1024, rowB = (size_t)(bm0 + r + 8) * 1024;
            #pragma unroll
            for (int nf = 0; nf < 16; nf++) {
                int gc = n_base + wn * 128 + nf * 8 + 2 * (lid & 3);
                float2 vb = *(const float2*)(g_vbar + gc);
                float2 o0 = make_float2(fmaf(acc[mi][nf][0], (1.0f / 512.0f), vb.x),
                                        fmaf(acc[mi][nf][1], (1.0f / 512.0f), vb.y));
                float2 o1 = make_float2(fmaf(acc[mi][nf][2], (1.0f / 512.0f), vb.x),
                                        fmaf(acc[mi][nf][3], (1.0f / 512.0f), vb.y));
                *(float2*)(outp + rowA + gc) = o0;
                *(float2*)(outp + rowB + gc) = o1;
            }
        }
    }
}

// ============================================================================
extern "C" void kernel_launch(void* const* d_in, const int* in_sizes, int n_in,
                              void* d_out, int out_size) {
    (void)in_sizes; (void)n_in; (void)out_size;
    const float* x  = (const float*)d_in[0];
    const float* kr = (const float*)d_in[1];
    const float* ki = (const float*)d_in[2];
    const float* vr = (const float*)d_in[3];
    const float* vi = (const float*)d_in[4];
    float* out = (float*)d_out;

    cudaFuncSetAttribute(gemm_kernel<0>, cudaFuncAttributeMaxDynamicSharedMemorySize, SMEM_BYTES);
    cudaFuncSetAttribute(gemm_kernel<1>, cudaFuncAttributeMaxDynamicSharedMemorySize, SMEM_BYTES);

    prep_kernel<<<3584, 256>>>(x, kr, ki, vr, vi);
    gemm_kernel<0><<<512, 256, SMEM_BYTES>>>(nullptr);
    gemm_kernel<1><<<dim3(512, 2), 256, SMEM_BYTES>>>(out);
}

// round 11
// speedup vs baseline: 1.0967x; 1.0431x over previous
#include <cuda_runtime.h>
#include <cuda_fp16.h>
#include <cstdint>
#include <cstddef>

// ============================================================================
// HolographicMemory on GB300 (base-sm_103 path): fp16 HMMA (f16 accum) +
// ldmatrix + cp.async, M=128 CTA tile, 512 threads (16 warps, 4x4), 2-stage.
//
//   prep : g_Xh = fp16(x); g_Kh[512x1024] = fp16([kr|ki]);
//          g_VT[1024x512] = fp16(V^T); g_vbar[1024] = colmean(V) fp32
//   G1   : energy = Xh * Kh^T (f16 acc); softmax; g_d = 512*attn - 1 (fp16)
//   G2   : out = vbar + (g_d * V) / 512   (B = VT, f16 acc)
// ============================================================================

#define TEMPERATURE 0.04419417382415922f   // 1/sqrt(512)

// ---------------- device scratch (no allocation allowed) --------------------
__device__ __half g_Xh[(size_t)32768 * 1024];
__device__ __half g_Kh[512 * 1024];
__device__ __half g_VT[1024 * 512];
__device__ float  g_vbar[1024];
__device__ __half g_d[(size_t)32768 * 512];

// ---------------- helpers ---------------------------------------------------
__device__ __forceinline__ uint32_t smem_u32(const void* p) {
    uint32_t a;
    asm("{ .reg .u64 t; cvta.to.shared.u64 t, %1; cvt.u32.u64 %0, t; }" : "=r"(a) : "l"(p));
    return a;
}
__device__ __forceinline__ uint32_t SWZ(uint32_t x) { return x ^ ((x >> 3) & 0x70); }

#define CP_ASYNC16(dst_u32, src_ptr) \
    asm volatile("cp.async.cg.shared.global [%0], [%1], 16;" :: "r"(dst_u32), "l"(src_ptr) : "memory")
#define CP_COMMIT() asm volatile("cp.async.commit_group;" ::: "memory")
#define CP_WAIT0()  asm volatile("cp.async.wait_group 0;" ::: "memory")

#define LDSM_X4(R, addr) \
    asm volatile("ldmatrix.sync.aligned.m8n8.x4.shared.b16 {%0,%1,%2,%3}, [%4];" \
        : "=r"((R)[0]), "=r"((R)[1]), "=r"((R)[2]), "=r"((R)[3]) : "r"(addr))

// m16n8k16 fp16 inputs, fp16 accumulators (2 packed regs)
__device__ __forceinline__ void mma16816h(uint32_t* c, const uint32_t* a, uint32_t b0, uint32_t b1) {
    asm volatile(
        "mma.sync.aligned.m16n8k16.row.col.f16.f16.f16.f16 "
        "{%0,%1}, {%2,%3,%4,%5}, {%6,%7}, {%0,%1};"
        : "+r"(c[0]), "+r"(c[1])
        : "r"(a[0]), "r"(a[1]), "r"(a[2]), "r"(a[3]), "r"(b0), "r"(b1));
}

// ---------------- smem layout: 2 pipeline stages ----------------------------
static constexpr int NSTAGE    = 2;
static constexpr int A_STAGE   = 16384;   // 128 x 64 fp16
static constexpr int B_STAGE   = 65536;   // 512 x 64 fp16
static constexpr int B_BASE    = NSTAGE * A_STAGE;               // 32768
static constexpr int SMEM_BYTES = NSTAGE * (A_STAGE + B_STAGE);  // 163840

// ============================================================================
// prep kernel: grid 3584 x 256 (unchanged; ~70% of HBM roofline)
// ============================================================================
__global__ void prep_kernel(const float* __restrict__ x,
                            const float* __restrict__ kr, const float* __restrict__ ki,
                            const float* __restrict__ vr, const float* __restrict__ vi) {
    int b = blockIdx.x, t = threadIdx.x;
    if (b < 2048) {
        size_t base = (size_t)b * 16384;
        const float4* src = (const float4*)(x + base);
        #pragma unroll
        for (int i = 0; i < 16; i++) {
            float4 v = src[t + i * 256];
            __half2 p0 = __float22half2_rn(make_float2(v.x, v.y));
            __half2 p1 = __float22half2_rn(make_float2(v.z, v.w));
            uint2 q = make_uint2(*(uint32_t*)&p0, *(uint32_t*)&p1);
            *(uint2*)(g_Xh + base + (size_t)(t + i * 256) * 4) = q;
        }
    } else if (b < 3072) {
        int h = b - 2048;
        const float* src = (h < 512) ? (vr + h) : (vi + (h - 512));
        float sum = 0.0f;
        for (int m = t; m < 512; m += 256) {
            float v = src[(size_t)m * 512];
            g_VT[(size_t)h * 512 + m] = __float2half(v);
            sum += v;
        }
        __shared__ float red[8];
        #pragma unroll
        for (int o = 16; o; o >>= 1) sum += __shfl_xor_sync(0xffffffffu, sum, o);
        if ((t & 31) == 0) red[t >> 5] = sum;
        __syncthreads();
        if (t == 0) {
            float s = 0.0f;
            #pragma unroll
            for (int i = 0; i < 8; i++) s += red[i];
            g_vbar[h] = s * (1.0f / 512.0f);
        }
    } else {
        int m = b - 3072;
        for (int c = t; c < 1024; c += 256) {
            float v = (c < 512) ? kr[(size_t)m * 512 + c] : ki[(size_t)m * 512 + c - 512];
            g_Kh[(size_t)m * 1024 + c] = __float2half(v);
        }
    }
}

// ============================================================================
// Unified GEMM: C[128 x 512] = A[128 x K] * B[512 x K]^T, K-chunked by 64.
//  MODE 0: A=g_Xh (K=1024), B=g_Kh, epilogue softmax -> g_d (d' = 512*attn-1)
//  MODE 1: A=g_d (K=512),  B=g_VT+n_base*512, epilogue vbar + acc/512 -> out
//  512 threads = 16 warps in 4(M) x 4(N); warp tile 32 x 128; f16 accumulators.
// ============================================================================
template <int MODE>
__global__ void __launch_bounds__(512, 1) gemm_kernel(float* __restrict__ outp) {
    constexpr int NC      = (MODE == 0) ? 16 : 8;
    constexpr int ASTRIDE = (MODE == 0) ? 1024 : 512;
    constexpr int BSTRIDE = (MODE == 0) ? 1024 : 512;

    extern __shared__ char S[];
    const uint32_t sb = smem_u32(S);

    const int tid = threadIdx.x, lid = tid & 31, w = tid >> 5;
    const int wm = w >> 2, wn = w & 3;            // warp grid 4(M) x 4(N)
    const int bm0 = blockIdx.x * 128;
    const int n_base = (MODE == 1) ? (int)blockIdx.y * 512 : 0;

    const __half* Asrc = (MODE == 0) ? (g_Xh + (size_t)bm0 * 1024)
                                     : (g_d  + (size_t)bm0 * 512);
    const __half* Bsrc = (MODE == 0) ? g_Kh : (g_VT + (size_t)n_base * 512);

    // ---- async chunk loader into stage st ----
    auto load_chunk = [&](int c, int st) {
        const int kc = c * 64;
        const uint32_t ab = sb + st * A_STAGE;
        const uint32_t bb = sb + B_BASE + st * B_STAGE;
        #pragma unroll
        for (int it = 0; it < 2; it++) {                 // A: 128 rows x 8 segs
            int u = tid + it * 512, row = u >> 3, seg = u & 7;
            const char* src = (const char*)(Asrc + (size_t)row * ASTRIDE + kc + seg * 8);
            CP_ASYNC16(ab + SWZ((uint32_t)(row * 128 + seg * 16)), src);
        }
        #pragma unroll
        for (int it = 0; it < 8; it++) {                 // B: 512 rows x 8 segs
            int u = tid + it * 512, row = u >> 3, seg = u & 7;
            const char* src = (const char*)(Bsrc + (size_t)row * BSTRIDE + kc + seg * 8);
            CP_ASYNC16(bb + SWZ((uint32_t)(row * 128 + seg * 16)), src);
        }
        CP_COMMIT();
    };

    // ---- per-thread ldmatrix byte offsets (pre-swizzle) ----
    uint32_t aoff[2], boff[8];
    #pragma unroll
    for (int mi = 0; mi < 2; mi++)
        aoff[mi] = (uint32_t)((wm * 32 + mi * 16 + (lid & 15)) * 128 + (lid >> 4) * 16);
    #pragma unroll
    for (int g = 0; g < 8; g++)
        boff[g] = (uint32_t)((wn * 128 + g * 16 + (lid & 15)) * 128 + (lid >> 4) * 16);

    // f16 accumulators: [mi][nf] -> 2 packed regs
    uint32_t hacc[2][16][2];
    #pragma unroll
    for (int mi = 0; mi < 2; mi++)
        #pragma unroll
        for (int nf = 0; nf < 16; nf++)
            hacc[mi][nf][0] = hacc[mi][nf][1] = 0u;

    auto compute = [&](int st) {
        const uint32_t ab = sb + st * A_STAGE;
        const uint32_t bb = sb + B_BASE + st * B_STAGE;
        #pragma unroll
        for (int ks = 0; ks < 4; ks++) {
            uint32_t a[2][4];
            #pragma unroll
            for (int mi = 0; mi < 2; mi++) LDSM_X4(a[mi], ab + SWZ(aoff[mi] + ks * 32));
            #pragma unroll
            for (int g = 0; g < 8; g++) {
                uint32_t bfrag[4];
                LDSM_X4(bfrag, bb + SWZ(boff[g] + ks * 32));
                #pragma unroll
                for (int mi = 0; mi < 2; mi++) {
                    mma16816h(hacc[mi][2 * g],     a[mi], bfrag[0], bfrag[2]);
                    mma16816h(hacc[mi][2 * g + 1], a[mi], bfrag[1], bfrag[3]);
                }
            }
        }
    };

    // ---- mainloop: 2-stage; load c+1 issued after barrier, overlaps compute c
    load_chunk(0, 0);
    #pragma unroll 1
    for (int c = 0; c < NC; c++) {
        CP_WAIT0();
        __syncthreads();          // chunk c visible; all warps done with stage (c+1)&1
        if (c + 1 < NC) load_chunk(c + 1, (c + 1) & 1);
        compute(c & 1);
    }
    __syncthreads();              // epilogue reuses smem

    // ---- expand f16 accumulators to fp32 ----
    float acc[2][16][4];
    #pragma unroll
    for (int mi = 0; mi < 2; mi++)
        #pragma unroll
        for (int nf = 0; nf < 16; nf++) {
            float2 lo = __half22float2(*(__half2*)&hacc[mi][nf][0]);
            float2 hi = __half22float2(*(__half2*)&hacc[mi][nf][1]);
            acc[mi][nf][0] = lo.x; acc[mi][nf][1] = lo.y;
            acc[mi][nf][2] = hi.x; acc[mi][nf][3] = hi.y;
        }

    // ---- epilogue ----
    if (MODE == 0) {
        float* red = (float*)S;   // 128 rows x 4 warps fp32 = 2 KB scratch
        #pragma unroll
        for (int mi = 0; mi < 2; mi++)
            #pragma unroll
            for (int nf = 0; nf < 16; nf++)
                #pragma unroll
                for (int j = 0; j < 4; j++)
                    acc[mi][nf][j] = __expf(acc[mi][nf][j] * TEMPERATURE);

        #pragma unroll
        for (int mi = 0; mi < 2; mi++) {
            float sA = 0.0f, sB = 0.0f;
            #pragma unroll
            for (int nf = 0; nf < 16; nf++) {
                sA += acc[mi][nf][0] + acc[mi][nf][1];
                sB += acc[mi][nf][2] + acc[mi][nf][3];
            }
            sA += __shfl_xor_sync(0xffffffffu, sA, 1);
            sA += __shfl_xor_sync(0xffffffffu, sA, 2);
            sB += __shfl_xor_sync(0xffffffffu, sB, 1);
            sB += __shfl_xor_sync(0xffffffffu, sB, 2);
            if ((lid & 3) == 0) {
                int r = wm * 32 + mi * 16 + (lid >> 2);
                red[r * 4 + wn]       = sA;
                red[(r + 8) * 4 + wn] = sB;
            }
        }
        __syncthreads();

        #pragma unroll
        for (int mi = 0; mi < 2; mi++) {
            int rA = wm * 32 + mi * 16 + (lid >> 2), rB = rA + 8;
            float scA = 512.0f / (red[rA * 4] + red[rA * 4 + 1] + red[rA * 4 + 2] + red[rA * 4 + 3]);
            float scB = 512.0f / (red[rB * 4] + red[rB * 4 + 1] + red[rB * 4 + 2] + red[rB * 4 + 3]);
            size_t baseA = (size_t)(bm0 + rA) * 512, baseB = (size_t)(bm0 + rB) * 512;
            #pragma unroll
            for (int nf = 0; nf < 16; nf++) {
                int gc = wn * 128 + nf * 8 + 2 * (lid & 3);
                __half2 pA = __float22half2_rn(make_float2(
                    acc[mi][nf][0] * scA - 1.0f, acc[mi][nf][1] * scA - 1.0f));
                __half2 pB = __float22half2_rn(make_float2(
                    acc[mi][nf][2] * scB - 1.0f, acc[mi][nf][3] * scB - 1.0f));
                *(uint32_t*)(g_d + baseA + gc) = *(uint32_t*)&pA;
                *(uint32_t*)(g_d + baseB + gc) = *(uint32_t*)&pB;
            }
        }
    } else {
        #pragma unroll
        for (int mi = 0; mi < 2; mi++) {
            int r = wm * 32 + mi * 16 + (lid >> 2);
            size_t rowA = (size_t)(bm0 + r) * 1024, rowB = (size_t)(bm0 + r + 8) * 1024;
            #pragma unroll
            for (int nf = 0; nf < 16; nf++) {
                int gc = n_base + wn * 128 + nf * 8 + 2 * (lid & 3);
                float2 vb = *(const float2*)(g_vbar + gc);
                float2 o0 = make_float2(fmaf(acc[mi][nf][0], (1.0f / 512.0f), vb.x),
                                        fmaf(acc[mi][nf][1], (1.0f / 512.0f), vb.y));
                float2 o1 = make_float2(fmaf(acc[mi][nf][2], (1.0f / 512.0f), vb.x),
                                        fmaf(acc[mi][nf][3], (1.0f / 512.0f), vb.y));
                *(float2*)(outp + rowA + gc) = o0;
                *(float2*)(outp + rowB + gc) = o1;
            }
        }
    }
}

// ============================================================================
extern "C" void kernel_launch(void* const* d_in, const int* in_sizes, int n_in,
                              void* d_out, int out_size) {
    (void)in_sizes; (void)n_in; (void)out_size;
    const float* x  = (const float*)d_in[0];
    const float* kr = (const float*)d_in[1];
    const float* ki = (const float*)d_in[2];
    const float* vr = (const float*)d_in[3];
    const float* vi = (const float*)d_in[4];
    float* out = (float*)d_out;

    cudaFuncSetAttribute(gemm_kernel<0>, cudaFuncAttributeMaxDynamicSharedMemorySize, SMEM_BYTES);
    cudaFuncSetAttribute(gemm_kernel<1>, cudaFuncAttributeMaxDynamicSharedMemorySize, SMEM_BYTES);

    prep_kernel<<<3584, 256>>>(x, kr, ki, vr, vi);
    gemm_kernel<0><<<256, 512, SMEM_BYTES>>>(nullptr);
    gemm_kernel<1><<<dim3(256, 2), 512, SMEM_BYTES>>>(out);
}